// round 4
// baseline (speedup 1.0000x reference)
#include <cuda_runtime.h>
#include <cuda_bf16.h>
#include <math.h>

// Problem dims (fixed)
#define Bv   16
#define Cv   256
#define Hv   32
#define Wv   32
#define Nv   16384          // B*H*W tokens
#define Ev   16384          // n_e codes
#define S0   4194304        // B*C*H*W = start of scalar outputs

// ---------------- device scratch (static, no allocs) ----------------
__device__ float              g_zf[(size_t)Nv * Cv];     // normalized tokens [N,C]
__device__ float              g_cn[Nv];                  // sum zf^2 per token
__device__ float              g_emb[(size_t)Ev * Cv];    // normalized codes [E,C]
__device__ float              g_sk[Ev];                  // sum emb^2 per code
__device__ float              g_t[(size_t)Nv * Ev];      // t = 200*G - 100*s_k (1 GiB)
__device__ unsigned long long g_rowmax[Nv];              // packed (ord(max t) << 32) | ~argmax
__device__ float              g_rowm[Nv];                // max t per row
__device__ float              g_rowr[Nv];                // 1/Z per row
__device__ int                g_idx[Nv];
__device__ float              g_avgp[Ev];                // sum_n p[n,k]
__device__ int                g_q[Bv];
__device__ float              g_acc[8];  // 0: masked dmin sum, 1: denom, 2: sample-ent sum, 3: avg-ent, 4: dead count

__device__ __forceinline__ unsigned int ford(float f) {
    unsigned int u = __float_as_uint(f);
    return (u & 0x80000000u) ? ~u : (u | 0x80000000u);
}

// ---------------- init: zero accumulators, decode query ids ----------------
__global__ void k_init(const void* qraw) {
    int i = blockIdx.x * blockDim.x + threadIdx.x;
    if (i < Ev) g_avgp[i] = 0.0f;
    if (i < Nv) g_rowmax[i] = 0ull;
    if (i == 0) {
        const unsigned int* w32 = (const unsigned int*)qraw;
        // int64 detection: high words of first 8 values must all be 0 (values < 32)
        bool is64 = true;
        for (int b = 0; b < 8; b++) if (w32[2 * b + 1] != 0u) is64 = false;
        int s = 0;
        for (int b = 0; b < Bv; b++) {
            int q = is64 ? (int)w32[2 * b] : (int)((const int*)qraw)[b];
            g_q[b] = q;
            s += q + 1;
        }
        for (int j = 0; j < 8; j++) g_acc[j] = 0.0f;
        g_acc[1] = (float)s;   // denom = sum_b (q_b + 1)   (mask is [B,1,W,1]!)
    }
}

// ---------------- normalize z: [B,C,H,W] -> zf[N,C] ----------------
__global__ __launch_bounds__(256) void k_norm_z(const float* __restrict__ z) {
    __shared__ float sm[Cv][Wv + 1];
    __shared__ float sinv[Wv];
    int bh = blockIdx.x;                 // b*32 + h
    int tid = threadIdx.x;
    const float* zp = z + (size_t)(bh >> 5) * Cv * (Hv * Wv) + (size_t)(bh & 31) * Wv;
    for (int it = 0; it < 32; ++it) {
        int l = it * 256 + tid;
        int c = l >> 5, w = l & 31;
        sm[c][w] = zp[(size_t)c * (Hv * Wv) + w];
    }
    __syncthreads();
    int w = tid >> 3, part = tid & 7;
    float s = 0.0f;
    for (int c = part; c < Cv; c += 8) { float v = sm[c][w]; s += v * v; }
    s += __shfl_xor_sync(~0u, s, 1);
    s += __shfl_xor_sync(~0u, s, 2);
    s += __shfl_xor_sync(~0u, s, 4);
    if (part == 0) {
        float inv = 1.0f / fmaxf(sqrtf(s), 1e-12f);
        sinv[w] = inv;
        g_cn[bh * 32 + w] = s * inv * inv;
    }
    __syncthreads();
    for (int w2 = 0; w2 < 32; ++w2) {
        int n = bh * 32 + w2;
        g_zf[(size_t)n * Cv + tid] = sm[tid][w2] * sinv[w2];
    }
}

// ---------------- normalize embedding ----------------
__global__ __launch_bounds__(256) void k_norm_emb(const float* __restrict__ e) {
    int k = blockIdx.x, tid = threadIdx.x;
    float v = e[(size_t)k * Cv + tid];
    float s = v * v;
    for (int o = 16; o; o >>= 1) s += __shfl_xor_sync(~0u, s, o);
    __shared__ float ws[8];
    if ((tid & 31) == 0) ws[tid >> 5] = s;
    __syncthreads();
    if (tid < 8) {
        float t = ws[tid];
        for (int o = 4; o; o >>= 1) t += __shfl_xor_sync(0xffu, t, o);
        if (tid == 0) ws[0] = t;
    }
    __syncthreads();
    float tot = ws[0];
    float inv = 1.0f / fmaxf(sqrtf(tot), 1e-12f);
    g_emb[(size_t)k * Cv + tid] = v * inv;
    if (tid == 0) g_sk[k] = tot * inv * inv;
}

// ---------------- main fp32 GEMM: t = 200*(zf . emb^T) - 100*s_k ----------------
// 128x128 tile, BK=32, 256 threads, 8x8 microtile (strided rows/cols)
__global__ __launch_bounds__(256) void k_gemm() {
    __shared__ float As[32][129];
    __shared__ float Bs[32][129];
    int tid = threadIdx.x;
    int tx = tid & 15, ty = tid >> 4;
    int bm = blockIdx.y * 128, bn = blockIdx.x * 128;
    float acc[8][8];
#pragma unroll
    for (int i = 0; i < 8; i++)
#pragma unroll
        for (int j = 0; j < 8; j++) acc[i][j] = 0.0f;

    const float* Ag = g_zf + (size_t)bm * Cv;
    const float* Bg = g_emb + (size_t)bn * Cv;
    int lr = tid >> 5;      // 0..7
    int lk = tid & 31;      // 0..31

    for (int kt = 0; kt < Cv; kt += 32) {
#pragma unroll
        for (int i = 0; i < 16; i++) {
            int r = i * 8 + lr;
            As[lk][r] = Ag[(size_t)r * Cv + kt + lk];
            Bs[lk][r] = Bg[(size_t)r * Cv + kt + lk];
        }
        __syncthreads();
#pragma unroll
        for (int k = 0; k < 32; k++) {
            float ra[8], rb[8];
#pragma unroll
            for (int i = 0; i < 8; i++) ra[i] = As[k][ty + 16 * i];
#pragma unroll
            for (int j = 0; j < 8; j++) rb[j] = Bs[k][tx + 16 * j];
#pragma unroll
            for (int i = 0; i < 8; i++)
#pragma unroll
                for (int j = 0; j < 8; j++) acc[i][j] += ra[i] * rb[j];
        }
        __syncthreads();
    }

    // epilogue: write t, fused per-row argmax
    float sk8[8];
    int cols[8];
#pragma unroll
    for (int j = 0; j < 8; j++) { cols[j] = bn + tx + 16 * j; sk8[j] = g_sk[cols[j]]; }
#pragma unroll
    for (int i = 0; i < 8; i++) {
        int row = bm + ty + 16 * i;
        float* trow = g_t + (size_t)row * Ev;
        float mv = -3.4e38f; int mc = 0x7fffffff;
#pragma unroll
        for (int j = 0; j < 8; j++) {
            float t = 200.0f * acc[i][j] - 100.0f * sk8[j];
            trow[cols[j]] = t;
            if (t > mv) { mv = t; mc = cols[j]; }   // cols ascend in j -> first wins ties
        }
#pragma unroll
        for (int o = 1; o < 16; o <<= 1) {
            float ov = __shfl_xor_sync(~0u, mv, o);
            int   oc = __shfl_xor_sync(~0u, mc, o);
            if (ov > mv || (ov == mv && oc < mc)) { mv = ov; mc = oc; }
        }
        if (tx == 0) {
            unsigned long long key =
                ((unsigned long long)ford(mv) << 32) |
                (unsigned long long)(0xFFFFFFFFu - (unsigned)mc);
            atomicMax(&g_rowmax[row], key);
        }
    }
}

// ---------------- row pass: Z, sum e^u * u, idx, masked dmin ----------------
__global__ __launch_bounds__(256) void k_rowstats() {
    int n = blockIdx.x, tid = threadIdx.x;
    unsigned long long key = g_rowmax[n];
    unsigned int o = (unsigned int)(key >> 32);
    unsigned int ub = (o & 0x80000000u) ? (o & 0x7FFFFFFFu) : ~o;
    float m = __uint_as_float(ub);
    int kidx = (int)(0xFFFFFFFFu - (unsigned int)(key & 0xFFFFFFFFull));

    const float4* row = (const float4*)(g_t + (size_t)n * Ev);
    float Z = 0.0f, U = 0.0f;
    for (int i = tid; i < Ev / 4; i += 256) {
        float4 v = row[i];
        float u0 = v.x - m, u1 = v.y - m, u2 = v.z - m, u3 = v.w - m;
        float e0 = __expf(u0), e1 = __expf(u1), e2 = __expf(u2), e3 = __expf(u3);
        Z += e0 + e1 + e2 + e3;
        U += e0 * u0 + e1 * u1 + e2 * u2 + e3 * u3;
    }
    for (int off = 16; off; off >>= 1) {
        Z += __shfl_xor_sync(~0u, Z, off);
        U += __shfl_xor_sync(~0u, U, off);
    }
    __shared__ float wz[8], wu[8];
    if ((tid & 31) == 0) { wz[tid >> 5] = Z; wu[tid >> 5] = U; }
    __syncthreads();
    if (tid == 0) {
        float Zt = 0.0f, Ut = 0.0f;
        for (int w = 0; w < 8; w++) { Zt += wz[w]; Ut += wu[w]; }
        g_rowm[n] = m;
        g_rowr[n] = 1.0f / Zt;
        g_idx[n] = kidx;
        atomicAdd(&g_acc[2], __logf(Zt) - Ut / Zt);   // per-row sample-entropy term
        float dmin = g_cn[n] - 0.01f * m;             // c_n + min(s_k - 2G)
        int b = n >> 10, w = n & 31;
        if (w <= g_q[b]) atomicAdd(&g_acc[0], dmin);
    }
}

// ---------------- column pass: avg_probs ----------------
__global__ __launch_bounds__(256) void k_colsum() {
    __shared__ float sm_m[512], sm_r[512];
    int col = blockIdx.x * 256 + threadIdx.x;
    int n0 = blockIdx.y * 512;
    for (int i = threadIdx.x; i < 512; i += 256) {
        sm_m[i] = g_rowm[n0 + i];
        sm_r[i] = g_rowr[n0 + i];
    }
    __syncthreads();
    float acc = 0.0f;
#pragma unroll 8
    for (int i = 0; i < 512; i++) {
        float t = g_t[(size_t)(n0 + i) * Ev + col];
        acc += __expf(t - sm_m[i]) * sm_r[i];
    }
    atomicAdd(&g_avgp[col], acc);
}

// ---------------- avg entropy ----------------
__global__ __launch_bounds__(256) void k_avgent() {
    int k = blockIdx.x * 256 + threadIdx.x;
    float ap = g_avgp[k] * (1.0f / (float)Nv);
    float v = -ap * __logf(ap + 1e-5f);
    for (int o = 16; o; o >>= 1) v += __shfl_xor_sync(~0u, v, o);
    __shared__ float ws[8];
    if ((threadIdx.x & 31) == 0) ws[threadIdx.x >> 5] = v;
    __syncthreads();
    if (threadIdx.x == 0) {
        float t = 0.0f;
        for (int w = 0; w < 8; w++) t += ws[w];
        atomicAdd(&g_acc[3], t);
    }
}

// ---------------- dead code rate ----------------
__global__ void k_dead() {   // <<<1,1024>>>
    int j = threadIdx.x;
    int v = g_idx[j];
    int same = 1;
    for (int b = 1; b < Bv; b++) same &= (g_idx[b * 1024 + j] == v);
    for (int o = 16; o; o >>= 1) same += __shfl_xor_sync(~0u, same, o);
    __shared__ int ws[32];
    if ((j & 31) == 0) ws[j >> 5] = same;
    __syncthreads();
    if (j < 32) {
        int t = ws[j];
        for (int o = 16; o; o >>= 1) t += __shfl_xor_sync(~0u, t, o);
        if (j == 0) g_acc[4] = (float)t;
    }
}

// ---------------- z_q straight-through output, transposed to [B,C,H,W] ----------------
__global__ __launch_bounds__(256) void k_output(float* __restrict__ out) {
    __shared__ float sm[Cv][Wv + 1];
    int bh = blockIdx.x, tid = threadIdx.x;
    for (int w = 0; w < 32; ++w) {
        int n = bh * 32 + w;
        int k = g_idx[n];
        float zf = g_zf[(size_t)n * Cv + tid];
        float e  = g_emb[(size_t)k * Cv + tid];
        sm[tid][w] = zf + (e - zf);   // forward value of STE, computed like the reference
    }
    __syncthreads();
    float* op = out + (size_t)(bh >> 5) * Cv * (Hv * Wv) + (size_t)(bh & 31) * Wv;
    for (int it = 0; it < 32; ++it) {
        int l = it * 256 + tid;
        int c = l >> 5, w = l & 31;
        op[(size_t)c * (Hv * Wv) + w] = sm[c][w];
    }
}

// ---------------- scalars + idx ----------------
__global__ void k_finalize(float* __restrict__ out, int out_size) {
    int i = blockIdx.x * blockDim.x + threadIdx.x;
    if (i < Nv && (S0 + 4 + i) < out_size) out[S0 + 4 + i] = (float)g_idx[i];
    if (i == 0 && (S0 + 3) < out_size) {
        float denom = g_acc[1];
        float vq = g_acc[0] / (256.0f * denom);
        out[S0 + 0] = vq;
        out[S0 + 1] = 0.25f * vq;                          // BETA * same forward value
        float sample = g_acc[2] * (1.0f / (float)Nv);
        out[S0 + 2] = 0.1f * (sample - g_acc[3]);          // ENTROPY_LOSS_RATIO
        out[S0 + 3] = g_acc[4] * (1.0f / 1024.0f);
    }
}

extern "C" void kernel_launch(void* const* d_in, const int* in_sizes, int n_in,
                              void* d_out, int out_size) {
    const float* z   = (const float*)d_in[0];
    const float* emb = (const float*)d_in[1];
    const void*  q   = d_in[2];
    float* out = (float*)d_out;

    k_init<<<64, 256>>>(q);
    k_norm_z<<<Bv * Hv, 256>>>(z);
    k_norm_emb<<<Ev, 256>>>(emb);
    dim3 gg(Ev / 128, Nv / 128);
    k_gemm<<<gg, 256>>>();
    k_rowstats<<<Nv, 256>>>();
    dim3 gc(Ev / 256, Nv / 512);
    k_colsum<<<gc, 256>>>();
    k_avgent<<<Ev / 256, 256>>>();
    k_dead<<<1, 1024>>>();
    k_output<<<Bv * Hv, 256>>>(out);
    k_finalize<<<64, 256>>>(out, out_size);
}

// round 9
// speedup vs baseline: 1.8465x; 1.8465x over previous
#include <cuda_runtime.h>
#include <cuda_bf16.h>
#include <math.h>
#include <stdint.h>

// Problem dims (fixed)
#define Bv   16
#define Cv   256
#define Hv   32
#define Wv   32
#define Nv   16384          // B*H*W tokens
#define Ev   16384          // n_e codes
#define S0   4194304        // B*C*H*W = start of scalar outputs

// GEMM tiling
#define KBIG 768            // [hi | lo | hi] x [hi | hi | lo]
#define BM   128
#define BN   128
#define BK   32
#define NKT  (KBIG / BK)    // 24 k-iterations
#define ROWB 80             // padded smem row stride in bytes
#define STG  (2 * BM * ROWB)        // 20480 bytes per stage (A + B)
#define SM_TOTAL (3 * STG)          // 61440

#define CAND_EPS 1e-2f
#define MAXCAND 32

// ---------------- device scratch (static, no allocs) ----------------
__device__ float              g_zf[(size_t)Nv * Cv];
__device__ float              g_cn[Nv];
__device__ float              g_emb[(size_t)Ev * Cv];
__device__ float              g_sk[Ev];
__device__ __align__(256) __nv_bfloat16 g_abig[(size_t)Nv * KBIG];
__device__ __align__(256) __nv_bfloat16 g_bbig[(size_t)Ev * KBIG];
__device__ float              g_t[(size_t)Nv * Ev];   // 1 GiB
__device__ unsigned long long g_rowmax[Nv];
__device__ float              g_rowm[Nv];
__device__ float              g_rowr[Nv];
__device__ int                g_idx[Nv];
__device__ float              g_avgp[Ev];
__device__ int                g_q[Bv];
__device__ float              g_acc[8];

__device__ __forceinline__ unsigned int ford(float f) {
    unsigned int u = __float_as_uint(f);
    return (u & 0x80000000u) ? ~u : (u | 0x80000000u);
}

// ---------------- PTX helpers (base-target only) ----------------
__device__ __forceinline__ uint32_t smem_u32(const void* p) {
    uint32_t a;
    asm("{ .reg .u64 t; cvta.to.shared.u64 t, %1; cvt.u32.u64 %0, t; }" : "=r"(a) : "l"(p));
    return a;
}
__device__ __forceinline__ void cp16(uint32_t dst, const void* src) {
    asm volatile("cp.async.cg.shared.global [%0], [%1], 16;" :: "r"(dst), "l"(src) : "memory");
}
__device__ __forceinline__ void cp_commit() {
    asm volatile("cp.async.commit_group;" ::: "memory");
}
template <int N>
__device__ __forceinline__ void cp_wait() {
    asm volatile("cp.async.wait_group %0;" :: "n"(N) : "memory");
}
__device__ __forceinline__ void hmma(float& c0, float& c1, float& c2, float& c3,
                                     uint32_t a0, uint32_t a1, uint32_t a2, uint32_t a3,
                                     uint32_t b0, uint32_t b1) {
    asm volatile(
        "mma.sync.aligned.m16n8k16.row.col.f32.bf16.bf16.f32 "
        "{%0,%1,%2,%3}, {%4,%5,%6,%7}, {%8,%9}, {%0,%1,%2,%3};"
        : "+f"(c0), "+f"(c1), "+f"(c2), "+f"(c3)
        : "r"(a0), "r"(a1), "r"(a2), "r"(a3), "r"(b0), "r"(b1));
}

// ---------------- init ----------------
__global__ void k_init(const void* qraw) {
    int i = blockIdx.x * blockDim.x + threadIdx.x;
    if (i < Ev) g_avgp[i] = 0.0f;
    if (i < Nv) g_rowmax[i] = 0ull;
    if (i == 0) {
        const unsigned int* w32 = (const unsigned int*)qraw;
        bool is64 = true;
        for (int b = 0; b < 8; b++) if (w32[2 * b + 1] != 0u) is64 = false;
        int s = 0;
        for (int b = 0; b < Bv; b++) {
            int q = is64 ? (int)w32[2 * b] : (int)((const int*)qraw)[b];
            g_q[b] = q;
            s += q + 1;
        }
        for (int j = 0; j < 8; j++) g_acc[j] = 0.0f;
        g_acc[1] = (float)s;
    }
}

// ---------------- normalize z + emit bf16 split ----------------
__global__ __launch_bounds__(256) void k_norm_z(const float* __restrict__ z) {
    __shared__ float sm[Cv][Wv + 1];
    __shared__ float sinv[Wv];
    int bh = blockIdx.x;
    int tid = threadIdx.x;
    const float* zp = z + (size_t)(bh >> 5) * Cv * (Hv * Wv) + (size_t)(bh & 31) * Wv;
    for (int it = 0; it < 32; ++it) {
        int l = it * 256 + tid;
        int c = l >> 5, w = l & 31;
        sm[c][w] = zp[(size_t)c * (Hv * Wv) + w];
    }
    __syncthreads();
    int w = tid >> 3, part = tid & 7;
    float s = 0.0f;
    for (int c = part; c < Cv; c += 8) { float v = sm[c][w]; s += v * v; }
    s += __shfl_xor_sync(~0u, s, 1);
    s += __shfl_xor_sync(~0u, s, 2);
    s += __shfl_xor_sync(~0u, s, 4);
    if (part == 0) {
        float inv = 1.0f / fmaxf(sqrtf(s), 1e-12f);
        sinv[w] = inv;
        g_cn[bh * 32 + w] = s * inv * inv;
    }
    __syncthreads();
    for (int w2 = 0; w2 < 32; ++w2) {
        int n = bh * 32 + w2;
        float v = sm[tid][w2] * sinv[w2];
        g_zf[(size_t)n * Cv + tid] = v;
        __nv_bfloat16 h = __float2bfloat16(v);
        __nv_bfloat16 l = __float2bfloat16(v - __bfloat162float(h));
        size_t base = (size_t)n * KBIG;
        g_abig[base + tid]       = h;
        g_abig[base + 256 + tid] = l;
        g_abig[base + 512 + tid] = h;
    }
}

// ---------------- normalize embedding + emit bf16 split ----------------
__global__ __launch_bounds__(256) void k_norm_emb(const float* __restrict__ e) {
    int k = blockIdx.x, tid = threadIdx.x;
    float v = e[(size_t)k * Cv + tid];
    float s = v * v;
    for (int o = 16; o; o >>= 1) s += __shfl_xor_sync(~0u, s, o);
    __shared__ float ws[8];
    if ((tid & 31) == 0) ws[tid >> 5] = s;
    __syncthreads();
    if (tid < 8) {
        float t = ws[tid];
        for (int o = 4; o; o >>= 1) t += __shfl_xor_sync(0xffu, t, o);
        if (tid == 0) ws[0] = t;
    }
    __syncthreads();
    float tot = ws[0];
    float inv = 1.0f / fmaxf(sqrtf(tot), 1e-12f);
    float vn = v * inv;
    g_emb[(size_t)k * Cv + tid] = vn;
    if (tid == 0) g_sk[k] = tot * inv * inv;
    __nv_bfloat16 h = __float2bfloat16(vn);
    __nv_bfloat16 l = __float2bfloat16(vn - __bfloat162float(h));
    size_t base = (size_t)k * KBIG;
    g_bbig[base + tid]       = h;
    g_bbig[base + 256 + tid] = h;
    g_bbig[base + 512 + tid] = l;
}

// ---------------- HMMA GEMM: t = 200*G - 100*s_k, fused row argmax ----------------
__device__ __forceinline__ void load_stage(uint32_t sbase, int s, const char* Ab,
                                           const char* Bb, int kt, int tid) {
    uint32_t base = sbase + s * STG;
    const char* Asrc = Ab + kt * (BK * 2);
#pragma unroll
    for (int i = 0; i < 2; i++) {
        int u = tid + i * 256;
        int r = u >> 2, c = u & 3;
        cp16(base + r * ROWB + c * 16, Asrc + (size_t)r * (KBIG * 2) + c * 16);
    }
    uint32_t bbase = base + BM * ROWB;
    const char* Bsrc = Bb + kt * (BK * 2);
#pragma unroll
    for (int i = 0; i < 2; i++) {
        int u = tid + i * 256;
        int r = u >> 2, c = u & 3;
        cp16(bbase + r * ROWB + c * 16, Bsrc + (size_t)r * (KBIG * 2) + c * 16);
    }
}

__global__ void __launch_bounds__(256) k_mma() {
    extern __shared__ char smem[];
    uint32_t sbase = smem_u32(smem);
    int tid = threadIdx.x, wid = tid >> 5, lane = tid & 31;
    int g = lane >> 2, tig = lane & 3;
    int warpM = wid >> 2, warpN = wid & 3;          // 2 x 4
    int bm = blockIdx.y * BM, bn = blockIdx.x * BN;

    const char* Ab = (const char*)g_abig + (size_t)bm * (KBIG * 2);
    const char* Bb = (const char*)g_bbig + (size_t)bn * (KBIG * 2);

    float acc[4][4][4];
#pragma unroll
    for (int mi = 0; mi < 4; mi++)
#pragma unroll
        for (int ni = 0; ni < 4; ni++)
#pragma unroll
            for (int r = 0; r < 4; r++) acc[mi][ni][r] = 0.0f;

    load_stage(sbase, 0, Ab, Bb, 0, tid); cp_commit();
    load_stage(sbase, 1, Ab, Bb, 1, tid); cp_commit();

    for (int kt = 0; kt < NKT; kt++) {
        cp_wait<1>();
        __syncthreads();
        if (kt + 2 < NKT) load_stage(sbase, (kt + 2) % 3, Ab, Bb, kt + 2, tid);
        cp_commit();

        const char* sA = smem + ((kt % 3) * STG);
        const char* sB = sA + BM * ROWB;
#pragma unroll
        for (int k16 = 0; k16 < 2; k16++) {
            int koff = k16 * 32 + tig * 4;
            uint32_t Ar[4][4];
#pragma unroll
            for (int mi = 0; mi < 4; mi++) {
                const char* p = sA + (warpM * 64 + mi * 16 + g) * ROWB + koff;
                Ar[mi][0] = *(const uint32_t*)(p);
                Ar[mi][1] = *(const uint32_t*)(p + 8 * ROWB);
                Ar[mi][2] = *(const uint32_t*)(p + 16);
                Ar[mi][3] = *(const uint32_t*)(p + 8 * ROWB + 16);
            }
            uint32_t Br[4][2];
#pragma unroll
            for (int ni = 0; ni < 4; ni++) {
                const char* p = sB + (warpN * 32 + ni * 8 + g) * ROWB + koff;
                Br[ni][0] = *(const uint32_t*)(p);
                Br[ni][1] = *(const uint32_t*)(p + 16);
            }
#pragma unroll
            for (int mi = 0; mi < 4; mi++)
#pragma unroll
                for (int ni = 0; ni < 4; ni++)
                    hmma(acc[mi][ni][0], acc[mi][ni][1], acc[mi][ni][2], acc[mi][ni][3],
                         Ar[mi][0], Ar[mi][1], Ar[mi][2], Ar[mi][3],
                         Br[ni][0], Br[ni][1]);
        }
        __syncthreads();
    }

    // epilogue
    int rowb = bm + warpM * 64;
    int colb = bn + warpN * 32;
    float skv[4][2];
#pragma unroll
    for (int ni = 0; ni < 4; ni++) {
        int c0 = colb + ni * 8 + 2 * tig;
        skv[ni][0] = __ldg(&g_sk[c0]);
        skv[ni][1] = __ldg(&g_sk[c0 + 1]);
    }
    float rv[4][2]; int rc[4][2];
#pragma unroll
    for (int mi = 0; mi < 4; mi++) { rv[mi][0] = rv[mi][1] = -3.4e38f; rc[mi][0] = rc[mi][1] = 0x7fffffff; }

#pragma unroll
    for (int mi = 0; mi < 4; mi++) {
        int r0 = rowb + mi * 16 + g;
        float* p0 = g_t + (size_t)r0 * Ev;
        float* p1 = g_t + (size_t)(r0 + 8) * Ev;
#pragma unroll
        for (int ni = 0; ni < 4; ni++) {
            int c0 = colb + ni * 8 + 2 * tig;
            float t00 = 200.0f * acc[mi][ni][0] - 100.0f * skv[ni][0];
            float t01 = 200.0f * acc[mi][ni][1] - 100.0f * skv[ni][1];
            float t10 = 200.0f * acc[mi][ni][2] - 100.0f * skv[ni][0];
            float t11 = 200.0f * acc[mi][ni][3] - 100.0f * skv[ni][1];
            *(float2*)(p0 + c0) = make_float2(t00, t01);
            *(float2*)(p1 + c0) = make_float2(t10, t11);
            if (t00 > rv[mi][0]) { rv[mi][0] = t00; rc[mi][0] = c0; }
            if (t01 > rv[mi][0]) { rv[mi][0] = t01; rc[mi][0] = c0 + 1; }
            if (t10 > rv[mi][1]) { rv[mi][1] = t10; rc[mi][1] = c0; }
            if (t11 > rv[mi][1]) { rv[mi][1] = t11; rc[mi][1] = c0 + 1; }
        }
    }
#pragma unroll
    for (int mi = 0; mi < 4; mi++)
#pragma unroll
        for (int h = 0; h < 2; h++) {
#pragma unroll
            for (int o = 1; o < 4; o <<= 1) {
                float ov = __shfl_xor_sync(~0u, rv[mi][h], o);
                int   oc = __shfl_xor_sync(~0u, rc[mi][h], o);
                if (ov > rv[mi][h] || (ov == rv[mi][h] && oc < rc[mi][h])) {
                    rv[mi][h] = ov; rc[mi][h] = oc;
                }
            }
            if (tig == 0) {
                int row = rowb + mi * 16 + g + h * 8;
                unsigned long long key =
                    ((unsigned long long)ford(rv[mi][h]) << 32) |
                    (unsigned long long)(0xFFFFFFFFu - (unsigned)rc[mi][h]);
                atomicMax(&g_rowmax[row], key);
            }
        }
}

// ---------------- row pass: Z, U, candidate collection + exact argmin refine ----------------
__global__ __launch_bounds__(256) void k_rowstats() {
    int n = blockIdx.x, tid = threadIdx.x;
    unsigned long long key = g_rowmax[n];
    unsigned int o = (unsigned int)(key >> 32);
    unsigned int ub = (o & 0x80000000u) ? (o & 0x7FFFFFFFu) : ~o;
    float m = __uint_as_float(ub);
    int kidx = (int)(0xFFFFFFFFu - (unsigned int)(key & 0xFFFFFFFFull));

    __shared__ int s_cand[MAXCAND];
    __shared__ int s_cnt;
    __shared__ int s_bidx;
    __shared__ float s_bt;
    if (tid == 0) { s_cnt = 0; s_bidx = kidx; s_bt = m; }
    __syncthreads();

    float thr = m - CAND_EPS;
    const float4* row = (const float4*)(g_t + (size_t)n * Ev);
    float Z = 0.0f, U = 0.0f;
    for (int i = tid; i < Ev / 4; i += 256) {
        float4 v = row[i];
        float u0 = v.x - m, u1 = v.y - m, u2 = v.z - m, u3 = v.w - m;
        float e0 = __expf(u0), e1 = __expf(u1), e2 = __expf(u2), e3 = __expf(u3);
        Z += e0 + e1 + e2 + e3;
        U += e0 * u0 + e1 * u1 + e2 * u2 + e3 * u3;
        if (v.x > thr) { int p = atomicAdd(&s_cnt, 1); if (p < MAXCAND) s_cand[p] = 4 * i; }
        if (v.y > thr) { int p = atomicAdd(&s_cnt, 1); if (p < MAXCAND) s_cand[p] = 4 * i + 1; }
        if (v.z > thr) { int p = atomicAdd(&s_cnt, 1); if (p < MAXCAND) s_cand[p] = 4 * i + 2; }
        if (v.w > thr) { int p = atomicAdd(&s_cnt, 1); if (p < MAXCAND) s_cand[p] = 4 * i + 3; }
    }
    for (int off = 16; off; off >>= 1) {
        Z += __shfl_xor_sync(~0u, Z, off);
        U += __shfl_xor_sync(~0u, U, off);
    }
    __shared__ float wz[8], wu[8];
    if ((tid & 31) == 0) { wz[tid >> 5] = Z; wu[tid >> 5] = U; }
    __syncthreads();

    // exact refinement (warp 0) when ambiguous: sequential-k fp32, R4-identical ordering
    int nc = min(s_cnt, MAXCAND);
    if (nc >= 2 && tid < 32) {
        float bt = -3.4e38f; int bc = 0x7fffffff;
        if (tid < nc) {
            int k = s_cand[tid];
            const float* ap = g_zf + (size_t)n * Cv;
            const float* bp = g_emb + (size_t)k * Cv;
            float dot = 0.0f;
#pragma unroll 8
            for (int c = 0; c < Cv; c++) dot = fmaf(__ldg(ap + c), __ldg(bp + c), dot);
            bt = 200.0f * dot - 100.0f * __ldg(&g_sk[k]);
            bc = k;
        }
#pragma unroll
        for (int off2 = 1; off2 < 32; off2 <<= 1) {
            float ov = __shfl_xor_sync(~0u, bt, off2);
            int   oc = __shfl_xor_sync(~0u, bc, off2);
            if (ov > bt || (ov == bt && oc < bc)) { bt = ov; bc = oc; }
        }
        if (tid == 0) { s_bidx = bc; s_bt = bt; }
    }
    __syncthreads();

    if (tid == 0) {
        float Zt = 0.0f, Ut = 0.0f;
        for (int w = 0; w < 8; w++) { Zt += wz[w]; Ut += wu[w]; }
        g_rowm[n] = m;
        g_rowr[n] = 1.0f / Zt;
        g_idx[n] = s_bidx;
        atomicAdd(&g_acc[2], __logf(Zt) - Ut / Zt);
        float dmin = g_cn[n] - 0.01f * s_bt;
        int b = n >> 10, w = n & 31;
        if (w <= g_q[b]) atomicAdd(&g_acc[0], dmin);
    }
}

// ---------------- column pass ----------------
__global__ __launch_bounds__(256) void k_colsum() {
    __shared__ float sm_m[512], sm_r[512];
    int col = blockIdx.x * 256 + threadIdx.x;
    int n0 = blockIdx.y * 512;
    for (int i = threadIdx.x; i < 512; i += 256) {
        sm_m[i] = g_rowm[n0 + i];
        sm_r[i] = g_rowr[n0 + i];
    }
    __syncthreads();
    float acc = 0.0f;
#pragma unroll 8
    for (int i = 0; i < 512; i++) {
        float t = g_t[(size_t)(n0 + i) * Ev + col];
        acc += __expf(t - sm_m[i]) * sm_r[i];
    }
    atomicAdd(&g_avgp[col], acc);
}

// ---------------- avg entropy ----------------
__global__ __launch_bounds__(256) void k_avgent() {
    int k = blockIdx.x * 256 + threadIdx.x;
    float ap = g_avgp[k] * (1.0f / (float)Nv);
    float v = -ap * __logf(ap + 1e-5f);
    for (int o = 16; o; o >>= 1) v += __shfl_xor_sync(~0u, v, o);
    __shared__ float ws[8];
    if ((threadIdx.x & 31) == 0) ws[threadIdx.x >> 5] = v;
    __syncthreads();
    if (threadIdx.x == 0) {
        float t = 0.0f;
        for (int w = 0; w < 8; w++) t += ws[w];
        atomicAdd(&g_acc[3], t);
    }
}

// ---------------- dead code rate ----------------
__global__ void k_dead() {
    int j = threadIdx.x;
    int v = g_idx[j];
    int same = 1;
    for (int b = 1; b < Bv; b++) same &= (g_idx[b * 1024 + j] == v);
    for (int o = 16; o; o >>= 1) same += __shfl_xor_sync(~0u, same, o);
    __shared__ int ws[32];
    if ((j & 31) == 0) ws[j >> 5] = same;
    __syncthreads();
    if (j < 32) {
        int t = ws[j];
        for (int o = 16; o; o >>= 1) t += __shfl_xor_sync(~0u, t, o);
        if (j == 0) g_acc[4] = (float)t;
    }
}

// ---------------- z_q output ----------------
__global__ __launch_bounds__(256) void k_output(float* __restrict__ out) {
    __shared__ float sm[Cv][Wv + 1];
    int bh = blockIdx.x, tid = threadIdx.x;
    for (int w = 0; w < 32; ++w) {
        int n = bh * 32 + w;
        int k = g_idx[n];
        float zf = g_zf[(size_t)n * Cv + tid];
        float e  = g_emb[(size_t)k * Cv + tid];
        sm[tid][w] = zf + (e - zf);
    }
    __syncthreads();
    float* op = out + (size_t)(bh >> 5) * Cv * (Hv * Wv) + (size_t)(bh & 31) * Wv;
    for (int it = 0; it < 32; ++it) {
        int l = it * 256 + tid;
        int c = l >> 5, w = l & 31;
        op[(size_t)c * (Hv * Wv) + w] = sm[c][w];
    }
}

// ---------------- scalars + idx ----------------
__global__ void k_finalize(float* __restrict__ out, int out_size) {
    int i = blockIdx.x * blockDim.x + threadIdx.x;
    if (i < Nv && (S0 + 4 + i) < out_size) out[S0 + 4 + i] = (float)g_idx[i];
    if (i == 0 && (S0 + 3) < out_size) {
        float denom = g_acc[1];
        float vq = g_acc[0] / (256.0f * denom);
        out[S0 + 0] = vq;
        out[S0 + 1] = 0.25f * vq;
        float sample = g_acc[2] * (1.0f / (float)Nv);
        out[S0 + 2] = 0.1f * (sample - g_acc[3]);
        out[S0 + 3] = g_acc[4] * (1.0f / 1024.0f);
    }
}

extern "C" void kernel_launch(void* const* d_in, const int* in_sizes, int n_in,
                              void* d_out, int out_size) {
    const float* z   = (const float*)d_in[0];
    const float* emb = (const float*)d_in[1];
    const void*  q   = d_in[2];
    float* out = (float*)d_out;

    cudaFuncSetAttribute(k_mma, cudaFuncAttributeMaxDynamicSharedMemorySize, SM_TOTAL);

    k_init<<<64, 256>>>(q);
    k_norm_z<<<Bv * Hv, 256>>>(z);
    k_norm_emb<<<Ev, 256>>>(emb);
    dim3 gg(Ev / BN, Nv / BM);    // 128 x 128 tiles
    k_mma<<<gg, 256, SM_TOTAL>>>();
    k_rowstats<<<Nv, 256>>>();
    dim3 gc(Ev / 256, Nv / 512);
    k_colsum<<<gc, 256>>>();
    k_avgent<<<Ev / 256, 256>>>();
    k_dead<<<1, 1024>>>();
    k_output<<<Bv * Hv, 256>>>(out);
    k_finalize<<<64, 256>>>(out, out_size);
}